// round 6
// baseline (speedup 1.0000x reference)
#include <cuda_runtime.h>
#include <math.h>

#define Bn 64
#define Sn 512
#define Hn 768
#define Tn 9
#define NCHUNK 32
#define CHUNK 16                         /* Sn / NCHUNK */
#define NCHTOT (Bn * NCHUNK)             /* 2048 chunks total */
#define CPB 12                           /* chunks per block (4 warps x 3) */
#define NBLK ((NCHTOT + CPB - 1) / CPB)  /* 171 */

// ---- static device scratch ----
__device__ float d_em[Bn * Sn * Tn];     // relu emissions
__device__ float d_ep[Bn * Sn * Tn];     // exp(relu emissions)
__device__ float d_CM[NCHTOT * 81];      // chunk transfer matrices (scaled 2^-CE)
__device__ int   d_CE[NCHTOT];           // chunk log2 scales
__device__ float d_sum;                  // final accumulator (zero-init)
__device__ unsigned d_cnt;               // batch ticket (zero-init)

// ============================================================
// Kernel A: emissions = relu(emb @ W^T + b); store em and exp(em).
// W staged ONCE per block in smem; inner-loop W reads are
// conflict-free broadcast LDS.128 (1 wavefront each) instead of
// 64B LDG through L1. emb stays direct coalesced float4 LDG with
// an 8-deep prefetch batch (32 lines in flight per warp).
// Warp = 8 rows x 4 k-lanes.
// ============================================================
__global__ __launch_bounds__(256) void emis_kernel(
    const float* __restrict__ emb,
    const float* __restrict__ W,
    const float* __restrict__ bias)
{
    __shared__ float4 Wsm[Tn * 192];   // 27648 B

    int tid  = threadIdx.x;

    // stage W (1728 float4), once
    {
        const float4* Wg = (const float4*)W;
        for (int i = tid; i < Tn * 192; i += 256) Wsm[i] = Wg[i];
    }
    __syncthreads();

    int lane = tid & 31;
    int warp = tid >> 5;
    int rsub = lane >> 2;          // row within warp (0..7)
    int q    = lane & 3;           // k-slice (0..3)
    int row  = blockIdx.x * 64 + warp * 8 + rsub;

    const float4* eg = (const float4*)emb + (size_t)row * (Hn / 4);

    float acc[Tn];
#pragma unroll
    for (int t = 0; t < Tn; t++) acc[t] = 0.f;

#pragma unroll 1
    for (int base = 0; base < 48; base += 8) {
        float4 eb[8];
#pragma unroll
        for (int u = 0; u < 8; u++)
            eb[u] = __ldg(eg + (q + 4 * (base + u)));
#pragma unroll
        for (int u = 0; u < 8; u++) {
            int k4 = q + 4 * (base + u);
            float4 e = eb[u];
#pragma unroll
            for (int t = 0; t < Tn; t++) {
                float4 w = Wsm[t * 192 + k4];   // broadcast LDS
                acc[t] = fmaf(e.x, w.x, acc[t]);
                acc[t] = fmaf(e.y, w.y, acc[t]);
                acc[t] = fmaf(e.z, w.z, acc[t]);
                acc[t] = fmaf(e.w, w.w, acc[t]);
            }
        }
    }

#pragma unroll
    for (int t = 0; t < Tn; t++) {
        acc[t] += __shfl_xor_sync(0xffffffffu, acc[t], 2);
        acc[t] += __shfl_xor_sync(0xffffffffu, acc[t], 1);
    }

    if (q == 0) {
        size_t b = (size_t)row * Tn;
#pragma unroll
        for (int t = 0; t < Tn; t++) {
            float v = acc[t] + __ldg(bias + t);
            v = v > 0.f ? v : 0.f;
            d_em[b + t] = v;
            d_ep[b + t] = __expf(v);
        }
    }
}

// ============================================================
// Kernel B: chunk transfer matrices, ROW-parallel (no shuffles).
// Lane = one matrix row: m[9] regs; eT (exp(trans), 81) in regs.
// Warp = 3 chunks (27 active lanes); block = 128 thr = 12 chunks.
// ============================================================
__global__ __launch_bounds__(128) void chunk_kernel(
    const int* __restrict__ labels,
    const int* __restrict__ mask,
    const float* __restrict__ trans)
{
    __shared__ float eTsm[81];
    __shared__ float Psm[CPB * CHUNK * Tn];   // 1728 floats
    __shared__ unsigned bitsm[CPB];
    __shared__ int tsm[CPB * Tn];

    int tid = threadIdx.x, w = tid >> 5, lane = tid & 31;

    if (tid < 81) eTsm[tid] = __expf(trans[tid]);

    int gbase = blockIdx.x * (CPB * CHUNK * Tn);
    for (int i = tid; i < CPB * CHUNK * Tn; i += 128) {
        int gi = gbase + i;
        Psm[i] = (gi < Bn * Sn * Tn) ? d_ep[gi] : 1.0f;
    }

#pragma unroll
    for (int r = 0; r < 2; r++) {
        int lc = r * 8 + 2 * w + (lane >> 4);
        int s = lane & 15;
        int cidx = blockIdx.x * CPB + lc;
        unsigned bit = 0;
        if (lc < CPB && cidx < NCHTOT) {
            int t = cidx * CHUNK + s;
            int lab = labels[t];
            int mk = mask[t];
            bit = (mk != 0 && lab != -100) ? 1u : 0u;
            if ((cidx & (NCHUNK - 1)) == 0 && s == 0) bit = 0;  // t==0 excluded
        }
        unsigned bal = __ballot_sync(0xffffffffu, bit);
        if ((lane == 0 || lane == 16) && lc < CPB)
            bitsm[lc] = (lane == 0) ? (bal & 0xFFFFu) : (bal >> 16);
    }
    __syncthreads();

    int u = lane < 27 ? lane / 9 : 0;
    int i = lane < 27 ? lane - 9 * u : 0;
    bool act = lane < 27;
    int lc = w * 3 + u;
    int cidx = blockIdx.x * CPB + lc;
    bool valid = act && (cidx < NCHTOT);

    float eTr[81];
#pragma unroll
    for (int x = 0; x < 81; x++) eTr[x] = eTsm[x];

    unsigned bits = bitsm[lc];
    const float* P = Psm + lc * (CHUNK * Tn);

    float m[9];
#pragma unroll
    for (int j = 0; j < 9; j++) m[j] = (j == i) ? 1.f : 0.f;
    int es = 0;

#pragma unroll 2
    for (int s = 0; s < CHUNK; s++) {
        bool take = ((bits >> s) & 1u) != 0;
        float a0 = 0.f, a1 = 0.f, a2 = 0.f, a3 = 0.f, a4 = 0.f;
        float a5 = 0.f, a6 = 0.f, a7 = 0.f, a8 = 0.f;
#pragma unroll
        for (int k = 0; k < 9; k++) {
            float mk = m[k];
            const float* e = &eTr[k * 9];
            a0 = fmaf(mk, e[0], a0); a1 = fmaf(mk, e[1], a1);
            a2 = fmaf(mk, e[2], a2); a3 = fmaf(mk, e[3], a3);
            a4 = fmaf(mk, e[4], a4); a5 = fmaf(mk, e[5], a5);
            a6 = fmaf(mk, e[6], a6); a7 = fmaf(mk, e[7], a7);
            a8 = fmaf(mk, e[8], a8);
        }
        float acc[9] = {a0, a1, a2, a3, a4, a5, a6, a7, a8};
#pragma unroll
        for (int j = 0; j < 9; j++) {
            float nv = acc[j] * P[s * Tn + j];
            m[j] = take ? nv : m[j];
        }
        if (s == 7) {
            float rm = m[0];
#pragma unroll
            for (int j = 1; j < 9; j++) rm = fmaxf(rm, m[j]);
            int e = (int)(__float_as_uint(rm) >> 23) - 127;
            float sc = __uint_as_float((unsigned)(127 - e) << 23);
#pragma unroll
            for (int j = 0; j < 9; j++) m[j] *= sc;
            es += e;
        }
    }

    float rm = m[0];
#pragma unroll
    for (int j = 1; j < 9; j++) rm = fmaxf(rm, m[j]);
    int r_i = (int)(__float_as_uint(rm) >> 23) - 127;
    if (act) tsm[lc * Tn + i] = es + r_i;
    __syncwarp();
    int emax = tsm[lc * Tn];
#pragma unroll
    for (int k = 1; k < 9; k++) emax = max(emax, tsm[lc * Tn + k]);
    float sc2 = exp2f((float)(es - emax));

    if (valid) {
        float* M = d_CM + (size_t)cidx * 81 + i * 9;
#pragma unroll
        for (int j = 0; j < 9; j++) M[j] = m[j] * sc2;
        if (i == 0) d_CE[cidx] = emax;
    }
}

// ============================================================
// Kernel C: per-batch combine + numerator; atomic mean finalize.
// ============================================================
__global__ __launch_bounds__(32) void combine_kernel(
    const int* __restrict__ labels,
    const int* __restrict__ mask,
    const float* __restrict__ trans,
    const float* __restrict__ startt,
    const float* __restrict__ endt,
    float* __restrict__ out)
{
    __shared__ float CMsm[NCHUNK * 81];
    int b = blockIdx.x;
    int lane = threadIdx.x;

    const float* CMg = d_CM + (size_t)b * NCHUNK * 81;
    for (int i = lane; i < NCHUNK * 81; i += 32) CMsm[i] = CMg[i];
    int es2 = d_CE[b * NCHUNK + lane];
    es2 = __reduce_add_sync(0xffffffffu, es2);

    float ps = 0.f;
    int cntm = 0;
    for (int t = lane; t < Sn; t += 32) {
        int lab2 = labels[b * Sn + t];
        bool vld = lab2 != -100;
        int lm = vld ? lab2 : 0;
        bool mb = (mask[b * Sn + t] != 0) && vld;
        if (mb) cntm++;
        if (mb && t >= 1) {
            int labp = labels[b * Sn + t - 1];
            int lmp = (labp != -100) ? labp : 0;
            ps += d_em[(size_t)(b * Sn + t) * Tn + lm] + __ldg(trans + lmp * Tn + lm);
        }
    }
#pragma unroll
    for (int o = 16; o > 0; o >>= 1) {
        ps += __shfl_xor_sync(0xffffffffu, ps, o);
        cntm += __shfl_xor_sync(0xffffffffu, cntm, o);
    }
    __syncwarp();

    int jx = lane < 9 ? lane : 0;
    float a = (lane < 9)
        ? __expf(__ldg(startt + jx)) * d_ep[(size_t)(b * Sn) * Tn + jx] : 0.f;

#pragma unroll 4
    for (int c2 = 0; c2 < NCHUNK; c2++) {
        float Mi[9];
#pragma unroll
        for (int i = 0; i < 9; i++) Mi[i] = CMsm[c2 * 81 + i * 9 + jx];
        float s = 0.f;
#pragma unroll
        for (int i = 0; i < 9; i++)
            s = fmaf(__shfl_sync(0xffffffffu, a, i), Mi[i], s);
        a = (lane < 9) ? s : 0.f;

        unsigned mx = __reduce_max_sync(0xffffffffu, __float_as_uint(a));
        int e = (int)(mx >> 23) - 127;
        float sc = __uint_as_float((unsigned)(127 - e) << 23);
        a *= sc;
        es2 += e;
    }

    float v = (lane < 9) ? a * __expf(__ldg(endt + jx)) : 0.f;
#pragma unroll
    for (int o = 16; o > 0; o >>= 1)
        v += __shfl_xor_sync(0xffffffffu, v, o);

    if (lane == 0) {
        float denom = (float)es2 * 0.69314718055994530942f + __logf(v);
        int l0 = labels[b * Sn];
        if (l0 == -100) l0 = 0;
        float first = __ldg(startt + l0) + d_em[(size_t)(b * Sn) * Tn + l0];
        int ll = labels[b * Sn + (cntm - 1)];
        if (ll == -100) ll = 0;
        float num = first + ps + __ldg(endt + ll);
        float nll = denom - num;

        atomicAdd(&d_sum, nll * (1.0f / (float)Bn));
        __threadfence();
        unsigned cdone = atomicAdd(&d_cnt, 1u);
        if (cdone == Bn - 1) {
            float tot = atomicAdd(&d_sum, 0.0f);
            out[0] = tot;
            atomicExch(&d_sum, 0.0f);
            atomicExch(&d_cnt, 0u);
        }
    }
}

// ============================================================
extern "C" void kernel_launch(void* const* d_in, const int* in_sizes, int n_in,
                              void* d_out, int out_size)
{
    const float* emb    = (const float*)d_in[0];
    const float* W      = (const float*)d_in[1];
    const float* bias   = (const float*)d_in[2];
    const float* startt = (const float*)d_in[3];
    const float* trans  = (const float*)d_in[4];
    const float* endt   = (const float*)d_in[5];
    const int*   labels = (const int*)d_in[6];
    const int*   mask   = (const int*)d_in[7];

    emis_kernel<<<512, 256>>>(emb, W, bias);
    chunk_kernel<<<NBLK, 128>>>(labels, mask, trans);
    combine_kernel<<<Bn, 32>>>(labels, mask, trans, startt, endt, (float*)d_out);
}